// round 5
// baseline (speedup 1.0000x reference)
#include <cuda_runtime.h>
#include <cuda_bf16.h>
#include <cstdint>

#define BTOT 16384
#define PWID 4416      // 64 z + 256 feat + 4096 zz
#define NCH  138       // PWID / 32
#define SQRTK 11.313708498984761f

__device__ __align__(16) __nv_bfloat16 g_Wh[64 * PWID];
__device__ __align__(16) __nv_bfloat16 g_Wl[64 * PWID];
__device__ float g_csq[64];
__device__ float g_bsum[64];

// ---------------- prep: fold chart_queries into weights ---------------------
__global__ void prep_fold(const float* __restrict__ qzw,
                          const float* __restrict__ qfw,
                          const float* __restrict__ qg,
                          const float* __restrict__ cq) {
  __shared__ float cq_s[64 * 128];
  const int tid = threadIdx.x;
  const float4* s4 = (const float4*)cq;
  float4* d4 = (float4*)cq_s;
  for (int i = tid; i < 2048; i += 256) d4[i] = s4[i];
  __syncthreads();

  const int pl = tid & 31;
  const int p  = blockIdx.x * 32 + pl;
  const int ng = tid >> 5;            // 8 groups, each does 8 charts
  const float* src; int stride, off;
  if (p < 64)       { src = qzw; stride = 64;   off = p; }
  else if (p < 320) { src = qfw; stride = 256;  off = p - 64; }
  else              { src = qg;  stride = 4096; off = p - 320; }

  float acc[8] = {0,0,0,0,0,0,0,0};
  for (int k = 0; k < 128; ++k) {
    float wv = src[(size_t)k * stride + off];
#pragma unroll
    for (int j = 0; j < 8; ++j)
      acc[j] = fmaf(cq_s[(ng * 8 + j) * 128 + k], wv, acc[j]);
  }
#pragma unroll
  for (int j = 0; j < 8; ++j) {
    size_t idx = (size_t)(ng * 8 + j) * PWID + p;
    float v = acc[j];
    __nv_bfloat16 h = __float2bfloat16(v);
    g_Wh[idx] = h;
    g_Wl[idx] = __float2bfloat16(v - __bfloat162float(h));
  }
}

__global__ void prep_small(const float* __restrict__ cq,
                           const float* __restrict__ qzb,
                           const float* __restrict__ qfb) {
  int n = threadIdx.x;
  if (n >= 64) return;
  const float* r = cq + n * 128;
  float cs = 0.f, bs = 0.f;
  for (int d = 0; d < 64; ++d) cs = fmaf(r[d], r[d], cs);
  for (int k = 0; k < 128; ++k) bs = fmaf(r[k], qzb[k] + qfb[k], bs);
  g_csq[n] = cs;
  g_bsum[n] = bs;
}

// --------------------------- main kernel ------------------------------------
// dyn smem layout (bytes)
#define O_ZS   0              // float [128][68]
#define O_CS   34816          // float [64][65]
#define O_SC   51456          // float [128][65]
#define O_XH   84736          // bf16  [128][40]
#define O_XL   94976          // bf16  [128][40]
#define O_WH   105216         // bf16  [64][40]
#define O_WL   110336         // bf16  [64][40]
#define O_ZSQ  115456         // float [128]
#define O_CSQ  115968         // float [64]
#define O_BSM  116224         // float [64]
#define O_RMX  116480         // float [128]
#define O_RIV  116992         // float [128]
#define SMEMB  117504

__device__ __forceinline__ void mma16816(float* c, const uint32_t* a,
                                         const uint32_t* b) {
  asm volatile(
      "mma.sync.aligned.m16n8k16.row.col.f32.bf16.bf16.f32 "
      "{%0,%1,%2,%3},{%4,%5,%6,%7},{%8,%9},{%0,%1,%2,%3};"
      : "+f"(c[0]), "+f"(c[1]), "+f"(c[2]), "+f"(c[3])
      : "r"(a[0]), "r"(a[1]), "r"(a[2]), "r"(a[3]), "r"(b[0]), "r"(b[1]));
}

__global__ void __launch_bounds__(256, 1)
atlas_main(const float* __restrict__ z, const float* __restrict__ feat,
           const float* __restrict__ cq, float* __restrict__ out,
           int out_size) {
  extern __shared__ char sm[];
  float* zs   = (float*)(sm + O_ZS);    // stride 68
  float* cs   = (float*)(sm + O_CS);    // stride 65
  float* Sc   = (float*)(sm + O_SC);    // stride 65
  __nv_bfloat16* Xh = (__nv_bfloat16*)(sm + O_XH); // stride 40
  __nv_bfloat16* Xl = (__nv_bfloat16*)(sm + O_XL); // stride 40
  __nv_bfloat16* Wh = (__nv_bfloat16*)(sm + O_WH); // stride 40
  __nv_bfloat16* Wl = (__nv_bfloat16*)(sm + O_WL); // stride 40
  float* zsq  = (float*)(sm + O_ZSQ);
  float* csqs = (float*)(sm + O_CSQ);
  float* bsm  = (float*)(sm + O_BSM);
  float* rmx  = (float*)(sm + O_RMX);
  float* riv  = (float*)(sm + O_RIV);

  const int tid = threadIdx.x;
  const int lane = tid & 31, w = tid >> 5;
  const int gid = lane >> 2, tg = lane & 3;
  const int r0 = blockIdx.x * 128;

  // load z block (128x64) and centers (64x64 = cq[:, :64])
  for (int i = tid; i < 2048; i += 256) {              // 2048 float4
    int row = i >> 4, q = i & 15;
    float4 v = ((const float4*)(z + (size_t)(r0 + row) * 64))[q];
    *(float4*)(zs + row * 68 + q * 4) = v;
  }
  for (int i = tid; i < 4096; i += 256) {
    int n = i >> 6, d = i & 63;
    cs[n * 65 + d] = cq[n * 128 + d];
  }
  if (tid < 64) { csqs[tid] = g_csq[tid]; bsm[tid] = g_bsum[tid]; }
  __syncthreads();
  if (tid < 128) {
    float s = 0.f;
    const float* zr = zs + tid * 68;
    for (int d = 0; d < 64; ++d) s = fmaf(zr[d], zr[d], s);
    zsq[tid] = s;
  }

  // mma accumulators: warp covers m 64 rows (wm) x n 16 cols (wn)
  const int wm = w >> 2, wn = w & 3;
  const int m_base = wm * 64, n_base = wn * 16;
  float acc[4][2][4];
#pragma unroll
  for (int a = 0; a < 4; ++a)
#pragma unroll
    for (int b = 0; b < 2; ++b)
#pragma unroll
      for (int q = 0; q < 4; ++q) acc[a][b][q] = 0.f;

  const int grow = tid >> 1, ghalf = tid & 1, gcb = ghalf * 16; // X gen role
  const int wn_row = tid >> 2, wseg = (tid & 3) * 8;            // W load role

  for (int c = 0; c < NCH; ++c) {
    const int p0 = c * 32;
    __syncthreads();   // protect X/W from previous iteration's readers
    // ---- generate X chunk (128 x 32) as hi/lo bf16 split ----
    float vals[16];
    if (c < 2) {
#pragma unroll
      for (int j = 0; j < 16; ++j) vals[j] = zs[grow * 68 + p0 + gcb + j];
    } else if (c < 10) {
      const float4* fp =
          (const float4*)(feat + (size_t)(r0 + grow) * 256 + (p0 - 64) + gcb);
#pragma unroll
      for (int q = 0; q < 4; ++q) {
        float4 v = fp[q];
        vals[q * 4 + 0] = v.x; vals[q * 4 + 1] = v.y;
        vals[q * 4 + 2] = v.z; vals[q * 4 + 3] = v.w;
      }
    } else {
      const int pz = p0 - 320;
      const int iz = pz >> 6, j0 = (pz & 63) + gcb;
      const float zi = zs[grow * 68 + iz];
#pragma unroll
      for (int j = 0; j < 16; ++j) vals[j] = zi * zs[grow * 68 + j0 + j];
    }
    uint32_t ph[8], plo[8];
#pragma unroll
    for (int j = 0; j < 8; ++j) {
      float v0 = vals[2 * j], v1 = vals[2 * j + 1];
      __nv_bfloat162 h2 = __float22bfloat162_rn(make_float2(v0, v1));
      ph[j] = *(uint32_t*)&h2;
      float r0f = v0 - __low2float(h2);
      float r1f = v1 - __high2float(h2);
      __nv_bfloat162 l2 = __float22bfloat162_rn(make_float2(r0f, r1f));
      plo[j] = *(uint32_t*)&l2;
    }
    *(uint4*)(Xh + grow * 40 + gcb)     = *(uint4*)(ph);
    *(uint4*)(Xh + grow * 40 + gcb + 8) = *(uint4*)(ph + 4);
    *(uint4*)(Xl + grow * 40 + gcb)     = *(uint4*)(plo);
    *(uint4*)(Xl + grow * 40 + gcb + 8) = *(uint4*)(plo + 4);
    // ---- load W chunk (64 x 32, hi+lo) ----
    *(uint4*)(Wh + wn_row * 40 + wseg) =
        *(const uint4*)(g_Wh + (size_t)wn_row * PWID + p0 + wseg);
    *(uint4*)(Wl + wn_row * 40 + wseg) =
        *(const uint4*)(g_Wl + (size_t)wn_row * PWID + p0 + wseg);
    __syncthreads();
    // ---- mma: 3-pass split (XhWh + XhWl + XlWh) over 2 k16 sub-chunks ----
#pragma unroll
    for (int kh = 0; kh < 2; ++kh) {
      const int k0 = kh * 16;
      uint32_t bh[2][2], bl[2][2];
#pragma unroll
      for (int nt = 0; nt < 2; ++nt) {
        const int n = n_base + nt * 8 + gid;
        bh[nt][0] = *(const uint32_t*)(Wh + n * 40 + k0 + tg * 2);
        bh[nt][1] = *(const uint32_t*)(Wh + n * 40 + k0 + tg * 2 + 8);
        bl[nt][0] = *(const uint32_t*)(Wl + n * 40 + k0 + tg * 2);
        bl[nt][1] = *(const uint32_t*)(Wl + n * 40 + k0 + tg * 2 + 8);
      }
#pragma unroll
      for (int mt = 0; mt < 4; ++mt) {
        const int m = m_base + mt * 16;
        uint32_t ah[4], al[4];
        ah[0] = *(const uint32_t*)(Xh + (m + gid) * 40 + k0 + tg * 2);
        ah[1] = *(const uint32_t*)(Xh + (m + gid + 8) * 40 + k0 + tg * 2);
        ah[2] = *(const uint32_t*)(Xh + (m + gid) * 40 + k0 + tg * 2 + 8);
        ah[3] = *(const uint32_t*)(Xh + (m + gid + 8) * 40 + k0 + tg * 2 + 8);
        al[0] = *(const uint32_t*)(Xl + (m + gid) * 40 + k0 + tg * 2);
        al[1] = *(const uint32_t*)(Xl + (m + gid + 8) * 40 + k0 + tg * 2);
        al[2] = *(const uint32_t*)(Xl + (m + gid) * 40 + k0 + tg * 2 + 8);
        al[3] = *(const uint32_t*)(Xl + (m + gid + 8) * 40 + k0 + tg * 2 + 8);
#pragma unroll
        for (int nt = 0; nt < 2; ++nt) {
          mma16816(acc[mt][nt], ah, bh[nt]);
          mma16816(acc[mt][nt], ah, bl[nt]);
          mma16816(acc[mt][nt], al, bh[nt]);
        }
      }
    }
  }
  __syncthreads();

  // ---- epilogue: fp32 z.c, hyperbolic score, store to Sc ----
  const int colA = n_base + tg * 2;            // 4 cols: colA,+1,+8,+9
#pragma unroll
  for (int mt = 0; mt < 4; ++mt) {
    const int row0 = m_base + mt * 16 + gid, row1 = row0 + 8;
    float zc[2][4] = {{0, 0, 0, 0}, {0, 0, 0, 0}};
    const float* z0 = zs + row0 * 68;
    const float* z1 = zs + row1 * 68;
    const float* c0 = cs + (colA)     * 65;
    const float* c1 = cs + (colA + 1) * 65;
    const float* c2 = cs + (colA + 8) * 65;
    const float* c3 = cs + (colA + 9) * 65;
    for (int d = 0; d < 64; ++d) {
      float a0 = z0[d], a1 = z1[d];
      float b0 = c0[d], b1 = c1[d], b2 = c2[d], b3 = c3[d];
      zc[0][0] = fmaf(a0, b0, zc[0][0]); zc[0][1] = fmaf(a0, b1, zc[0][1]);
      zc[0][2] = fmaf(a0, b2, zc[0][2]); zc[0][3] = fmaf(a0, b3, zc[0][3]);
      zc[1][0] = fmaf(a1, b0, zc[1][0]); zc[1][1] = fmaf(a1, b1, zc[1][1]);
      zc[1][2] = fmaf(a1, b2, zc[1][2]); zc[1][3] = fmaf(a1, b3, zc[1][3]);
    }
#pragma unroll
    for (int nt = 0; nt < 2; ++nt) {
#pragma unroll
      for (int q = 0; q < 4; ++q) {
        const int rh = q >> 1;                   // 0: row0, 1: row1
        const int row = rh ? row1 : row0;
        const int col = colA + nt * 8 + (q & 1);
        const float gem = acc[mt][nt][q];
        const float zq = zsq[row], cq2 = csqs[col];
        const float zcv = zc[rh][nt * 2 + (q & 1)];
        float dsq = zq + cq2 - 2.f * zcv;
        float denom = (1.f - zq) * (1.f - cq2) + 1e-3f;
        float arg = 1.f + 2.f * dsq / denom;
        arg = fmaxf(arg, 1.001f);
        // acosh(x) = log(x + sqrt((x+1)(x-1)))  (XLA-style, no x^2-1 cancel)
        float dist = logf(arg + sqrtf((arg + 1.f) * (arg - 1.f)));
        float tau = fmaxf(SQRTK * fmaxf(1.f - zq, 1e-3f) * 0.5f, 0.01f);
        float r2 = fminf(zq, 0.999f);
        float invlam = (1.f - r2 + 1e-3f) * 0.5f;
        Sc[row * 65 + col] =
            -dist / tau + (gem + bsm[col]) * invlam * (1.f / SQRTK);
      }
    }
  }
  __syncthreads();

  // ---- softmax + argmax ----
  const bool has_k = (out_size >= BTOT * 64 + BTOT);
  if (tid < 128) {
    float m = -1e30f; int am = 0;
    const float* sr = Sc + tid * 65;
    for (int n = 0; n < 64; ++n) {
      float v = sr[n];
      if (v > m) { m = v; am = n; }
    }
    float s = 0.f;
    for (int n = 0; n < 64; ++n) s += __expf(sr[n] - m);
    rmx[tid] = m;
    riv[tid] = 1.f / s;
    if (has_k) out[BTOT * 64 + r0 + tid] = (float)am;
  }
  __syncthreads();
  for (int i = tid; i < 8192; i += 256) {
    int r = i >> 6, n = i & 63;
    out[(size_t)(r0 + r) * 64 + n] =
        __expf(Sc[r * 65 + n] - rmx[r]) * riv[r];
  }
}

// ----------------------------------------------------------------------------
extern "C" void kernel_launch(void* const* d_in, const int* in_sizes, int n_in,
                              void* d_out, int out_size) {
  const float* z    = (const float*)d_in[0];
  const float* feat = (const float*)d_in[1];
  const float* qzw  = (const float*)d_in[2];
  const float* qzb  = (const float*)d_in[3];
  const float* qfw  = (const float*)d_in[4];
  const float* qfb  = (const float*)d_in[5];
  const float* qg   = (const float*)d_in[6];
  const float* cq   = (const float*)d_in[7];
  float* out = (float*)d_out;

  prep_fold<<<NCH, 256>>>(qzw, qfw, qg, cq);
  prep_small<<<1, 64>>>(cq, qzb, qfb);
  cudaFuncSetAttribute(atlas_main, cudaFuncAttributeMaxDynamicSharedMemorySize,
                       SMEMB);
  atlas_main<<<BTOT / 128, 256, SMEMB>>>(z, feat, cq, out, out_size);
}

// round 6
// speedup vs baseline: 1.4436x; 1.4436x over previous
#include <cuda_runtime.h>
#include <cuda_bf16.h>
#include <cstdint>

#define BTOT 16384
#define PFULL 4416          // 64 z + 256 feat + 4096 zz (full)
#define PW2   2432          // 64 z + 256 feat + 2080 zz-tri + 32 pad
#define NCH   38            // PW2 / 64
#define SQRTK 11.313708498984761f

__device__ float g_Wfull[64 * PFULL];
__device__ __align__(16) __nv_bfloat16 g_Wh[64 * PW2];
__device__ __align__(16) __nv_bfloat16 g_Wl[64 * PW2];
__device__ float g_csq[64];
__device__ float g_bsum[64];
__device__ unsigned char g_pi[PW2], g_pj[PW2];

// ---------------- prep stage 1: full fp32 fold over K=128 -------------------
__global__ void prep_fold1(const float* __restrict__ qzw,
                           const float* __restrict__ qfw,
                           const float* __restrict__ qg,
                           const float* __restrict__ cq) {
  __shared__ float cq_s[64 * 128];
  const int tid = threadIdx.x;
  const float4* s4 = (const float4*)cq;
  float4* d4 = (float4*)cq_s;
  for (int i = tid; i < 2048; i += 256) d4[i] = s4[i];
  __syncthreads();

  const int p  = blockIdx.x * 32 + (tid & 7) * 4;   // float4 of p
  const int ng = tid >> 3;                          // 32 groups x 2 charts
  const float* src; int stride, off;
  if (p < 64)       { src = qzw; stride = 64;   off = p; }
  else if (p < 320) { src = qfw; stride = 256;  off = p - 64; }
  else              { src = qg;  stride = 4096; off = p - 320; }

  float acc[2][4] = {};
  for (int k0 = 0; k0 < 128; k0 += 4) {
    float4 wv[4];
#pragma unroll
    for (int kk = 0; kk < 4; ++kk)
      wv[kk] = *(const float4*)(src + (size_t)(k0 + kk) * stride + off);
#pragma unroll
    for (int kk = 0; kk < 4; ++kk) {
#pragma unroll
      for (int j = 0; j < 2; ++j) {
        float cv = cq_s[(ng * 2 + j) * 128 + k0 + kk];
        acc[j][0] = fmaf(cv, wv[kk].x, acc[j][0]);
        acc[j][1] = fmaf(cv, wv[kk].y, acc[j][1]);
        acc[j][2] = fmaf(cv, wv[kk].z, acc[j][2]);
        acc[j][3] = fmaf(cv, wv[kk].w, acc[j][3]);
      }
    }
  }
#pragma unroll
  for (int j = 0; j < 2; ++j)
    *(float4*)(g_Wfull + (size_t)(ng * 2 + j) * PFULL + p) = *(float4*)acc[j];
}

// ------- prep stage 2: symmetric triangle fold + hi/lo split + tables -------
__global__ void prep_fold2() {
  const int tid = threadIdx.x;
  const int pl = blockIdx.x * 64 + (tid & 63);
  const int ng = tid >> 6;                 // 4 groups x 16 charts
  int srcp = -1, srcq = -1, pi = 0, pj = 0;
  if (pl < 320) {
    srcp = pl;
  } else {
    int t = pl - 320;
    if (t < 2080) {                        // upper-tri packed index
      int i = 0, rem = t;
      while (rem >= 64 - i) { rem -= 64 - i; ++i; }
      int j = i + rem;
      pi = i; pj = j;
      srcp = 320 + i * 64 + j;
      srcq = (j > i) ? (320 + j * 64 + i) : -1;
    }
  }
  if (ng == 0) { g_pi[pl] = (unsigned char)pi; g_pj[pl] = (unsigned char)pj; }
#pragma unroll 4
  for (int jj = 0; jj < 16; ++jj) {
    int n = ng * 16 + jj;
    float v = 0.f;
    if (srcp >= 0) {
      v = g_Wfull[(size_t)n * PFULL + srcp];
      if (srcq >= 0) v += g_Wfull[(size_t)n * PFULL + srcq];
    }
    __nv_bfloat16 h = __float2bfloat16(v);
    g_Wh[(size_t)n * PW2 + pl] = h;
    g_Wl[(size_t)n * PW2 + pl] = __float2bfloat16(v - __bfloat162float(h));
  }
}

__global__ void prep_small(const float* __restrict__ cq,
                           const float* __restrict__ qzb,
                           const float* __restrict__ qfb) {
  int n = threadIdx.x;
  if (n >= 64) return;
  const float* r = cq + n * 128;
  float cs = 0.f, bs = 0.f;
  for (int d = 0; d < 64; ++d) cs = fmaf(r[d], r[d], cs);
  for (int k = 0; k < 128; ++k) bs = fmaf(r[k], qzb[k] + qfb[k], bs);
  g_csq[n] = cs;
  g_bsum[n] = bs;
}

// --------------------------- main kernel ------------------------------------
// smem layout (bytes)
#define O_ZS   0             // float [128][68] = 34816
#define O_CS   34816         // float [64][65]  = 16640
#define O_TB   51456         // uchar pi[2432] + pj[2432] = 4864
#define O_ZSQ  56320         // float [128]
#define O_CSQ  56832
#define O_BSM  57088
#define O_RMX  57344
#define O_RIV  57856
#define O_XH   58368         // bf16 [2][128][72] = 36864  (Sc overlaps here)
#define O_XL   95232         // bf16 [2][128][72] = 36864
#define O_WH   132096        // bf16 [2][64][72]  = 18432
#define O_WL   150528        // bf16 [2][64][72]  = 18432
#define SMEMB  168960

__device__ __forceinline__ void mma16816(float* c, const uint32_t* a,
                                         const uint32_t* b) {
  asm volatile(
      "mma.sync.aligned.m16n8k16.row.col.f32.bf16.bf16.f32 "
      "{%0,%1,%2,%3},{%4,%5,%6,%7},{%8,%9},{%0,%1,%2,%3};"
      : "+f"(c[0]), "+f"(c[1]), "+f"(c[2]), "+f"(c[3])
      : "r"(a[0]), "r"(a[1]), "r"(a[2]), "r"(a[3]), "r"(b[0]), "r"(b[1]));
}

__device__ __forceinline__ void ldsm4(uint32_t* r, uint32_t saddr) {
  asm volatile(
      "ldmatrix.sync.aligned.m8n8.x4.shared.b16 {%0,%1,%2,%3},[%4];"
      : "=r"(r[0]), "=r"(r[1]), "=r"(r[2]), "=r"(r[3]) : "r"(saddr));
}

__device__ __forceinline__ void pack_store(__nv_bfloat16* xh, __nv_bfloat16* xl,
                                           const float* v) {
  uint32_t ph[4], plo[4];
#pragma unroll
  for (int j = 0; j < 4; ++j) {
    __nv_bfloat162 h2 = __float22bfloat162_rn(make_float2(v[2 * j], v[2 * j + 1]));
    ph[j] = *(uint32_t*)&h2;
    __nv_bfloat162 l2 = __float22bfloat162_rn(
        make_float2(v[2 * j] - __low2float(h2), v[2 * j + 1] - __high2float(h2)));
    plo[j] = *(uint32_t*)&l2;
  }
  *(uint4*)xh = *(uint4*)ph;
  *(uint4*)xl = *(uint4*)plo;
}

__global__ void __launch_bounds__(256, 1)
atlas_main(const float* __restrict__ z, const float* __restrict__ feat,
           const float* __restrict__ cq, float* __restrict__ out,
           int out_size) {
  extern __shared__ char sm[];
  float* zs = (float*)(sm + O_ZS);                 // stride 68
  float* cs = (float*)(sm + O_CS);                 // stride 65
  unsigned char* tpi = (unsigned char*)(sm + O_TB);
  unsigned char* tpj = tpi + PW2;
  float* zsq  = (float*)(sm + O_ZSQ);
  float* csqs = (float*)(sm + O_CSQ);
  float* bsm  = (float*)(sm + O_BSM);
  float* rmx  = (float*)(sm + O_RMX);
  float* riv  = (float*)(sm + O_RIV);
  float* Sc   = (float*)(sm + O_XH);               // overlap, used post-MMA
  __nv_bfloat16* Xh = (__nv_bfloat16*)(sm + O_XH); // per-buf 9216 elem
  __nv_bfloat16* Xl = (__nv_bfloat16*)(sm + O_XL);
  __nv_bfloat16* Wh = (__nv_bfloat16*)(sm + O_WH); // per-buf 4608 elem
  __nv_bfloat16* Wl = (__nv_bfloat16*)(sm + O_WL);

  const int tid = threadIdx.x, lane = tid & 31, w = tid >> 5;
  const int gid = lane >> 2, tg = lane & 3;
  const int r0 = blockIdx.x * 128;
  const uint32_t smb = (uint32_t)__cvta_generic_to_shared(sm);

  for (int i = tid; i < 2048; i += 256) {
    int row = i >> 4, q = i & 15;
    *(float4*)(zs + row * 68 + q * 4) =
        ((const float4*)(z + (size_t)(r0 + row) * 64))[q];
  }
  for (int i = tid; i < 4096; i += 256) {
    int n = i >> 6, d = i & 63;
    cs[n * 65 + d] = cq[n * 128 + d];
  }
  for (int i = tid; i < PW2; i += 256) { tpi[i] = g_pi[i]; tpj[i] = g_pj[i]; }
  if (tid < 64) { csqs[tid] = g_csq[tid]; bsm[tid] = g_bsum[tid]; }
  __syncthreads();
  if (tid < 128) {
    float s = 0.f;
    const float* zr = zs + tid * 68;
    for (int d = 0; d < 64; ++d) s = fmaf(zr[d], zr[d], s);
    zsq[tid] = s;
  }

  const int grow = tid >> 1, ghalf = tid & 1;   // X-gen role
  const float* zrow = zs + grow * 68;
  const int wrow = tid >> 2, wcol = (tid & 3) * 16;  // W-load role

  // prologue: chunk 0 (z region) + W0 into buf 0
  {
#pragma unroll
    for (int g = 0; g < 4; ++g) {
      int pb = ghalf * 32 + g * 8;
      float v[8];
#pragma unroll
      for (int j = 0; j < 8; ++j) v[j] = zrow[pb + j];
      pack_store(Xh + grow * 72 + pb, Xl + grow * 72 + pb, v);
    }
    const __nv_bfloat16* gh = g_Wh + (size_t)wrow * PW2 + wcol;
    const __nv_bfloat16* gl = g_Wl + (size_t)wrow * PW2 + wcol;
    *(uint4*)(Wh + wrow * 72 + wcol)     = *(const uint4*)gh;
    *(uint4*)(Wh + wrow * 72 + wcol + 8) = *(const uint4*)(gh + 8);
    *(uint4*)(Wl + wrow * 72 + wcol)     = *(const uint4*)gl;
    *(uint4*)(Wl + wrow * 72 + wcol + 8) = *(const uint4*)(gl + 8);
  }
  __syncthreads();

  const int wm = w >> 2, wn = w & 3;
  const int m_base = wm * 64, n_base = wn * 16;
  float acc[4][2][4] = {};

  const uint32_t aoff = ((lane & 15) * 72 + (lane >> 4) * 8) * 2;
  const uint32_t boff =
      (((((lane >> 4) << 3)) + (lane & 7)) * 72 + ((lane >> 3) & 1) * 8) * 2;
  const uint32_t XHb = smb + O_XH + m_base * 144 + aoff;
  const uint32_t XLb = smb + O_XL + m_base * 144 + aoff;
  const uint32_t WHb = smb + O_WH + n_base * 144 + boff;
  const uint32_t WLb = smb + O_WL + n_base * 144 + boff;

  for (int c = 0; c < NCH; ++c) {
    const int cb = c & 1, nb = cb ^ 1, cc = c + 1;
    // stage next W chunk (LDG latency hidden under MMAs)
    uint4 whr[2], wlr[2];
    if (cc < NCH) {
      const __nv_bfloat16* gh = g_Wh + (size_t)wrow * PW2 + cc * 64 + wcol;
      const __nv_bfloat16* gl = g_Wl + (size_t)wrow * PW2 + cc * 64 + wcol;
      whr[0] = *(const uint4*)gh; whr[1] = *(const uint4*)(gh + 8);
      wlr[0] = *(const uint4*)gl; wlr[1] = *(const uint4*)(gl + 8);
    }
    // MMA on buf cb (3-pass split, 64-wide K)
    const uint32_t xh0 = XHb + cb * 18432, xl0 = XLb + cb * 18432;
    const uint32_t wh0 = WHb + cb * 9216,  wl0 = WLb + cb * 9216;
#pragma unroll
    for (int kh = 0; kh < 4; ++kh) {
      const uint32_t kb = kh * 32;
      uint32_t bh[4], bl[4];
      ldsm4(bh, wh0 + kb);
      ldsm4(bl, wl0 + kb);
#pragma unroll
      for (int mt = 0; mt < 4; ++mt) {
        uint32_t ah[4], al[4];
        ldsm4(ah, xh0 + mt * 2304 + kb);
        ldsm4(al, xl0 + mt * 2304 + kb);
#pragma unroll
        for (int nt = 0; nt < 2; ++nt) {
          mma16816(acc[mt][nt], ah, bh + nt * 2);
          mma16816(acc[mt][nt], ah, bl + nt * 2);
          mma16816(acc[mt][nt], al, bh + nt * 2);
        }
      }
    }
    // produce chunk cc into buf nb
    if (cc < NCH) {
      __nv_bfloat16* xhd = Xh + nb * 9216 + grow * 72 + ghalf * 32;
      __nv_bfloat16* xld = Xl + nb * 9216 + grow * 72 + ghalf * 32;
      const int pb = cc * 64 + ghalf * 32;
      if (cc < 5) {                       // feat region
        const float* fp = feat + (size_t)(r0 + grow) * 256 + (pb - 64);
#pragma unroll
        for (int g = 0; g < 4; ++g) {
          float v[8];
          float4 u0 = *(const float4*)(fp + g * 8);
          float4 u1 = *(const float4*)(fp + g * 8 + 4);
          v[0] = u0.x; v[1] = u0.y; v[2] = u0.z; v[3] = u0.w;
          v[4] = u1.x; v[5] = u1.y; v[6] = u1.z; v[7] = u1.w;
          pack_store(xhd + g * 8, xld + g * 8, v);
        }
      } else {                            // zz triangle region
#pragma unroll
        for (int g = 0; g < 4; ++g) {
          float v[8];
#pragma unroll
          for (int j = 0; j < 8; ++j) {
            int p = pb + g * 8 + j;
            v[j] = zrow[tpi[p]] * zrow[tpj[p]];
          }
          pack_store(xhd + g * 8, xld + g * 8, v);
        }
      }
      *(uint4*)(Wh + nb * 4608 + wrow * 72 + wcol)     = whr[0];
      *(uint4*)(Wh + nb * 4608 + wrow * 72 + wcol + 8) = whr[1];
      *(uint4*)(Wl + nb * 4608 + wrow * 72 + wcol)     = wlr[0];
      *(uint4*)(Wl + nb * 4608 + wrow * 72 + wcol + 8) = wlr[1];
    }
    __syncthreads();
  }

  // ---- epilogue: fp32 z.c, hyperbolic score (Sc overlaps dead X buffer) ----
  const int colA = n_base + tg * 2;
#pragma unroll
  for (int mt = 0; mt < 4; ++mt) {
    const int row0 = m_base + mt * 16 + gid, row1 = row0 + 8;
    float zc[2][4] = {{0, 0, 0, 0}, {0, 0, 0, 0}};
    const float* z0 = zs + row0 * 68;
    const float* z1 = zs + row1 * 68;
    const float* c0 = cs + (colA)     * 65;
    const float* c1 = cs + (colA + 1) * 65;
    const float* c2 = cs + (colA + 8) * 65;
    const float* c3 = cs + (colA + 9) * 65;
    for (int d = 0; d < 64; ++d) {
      float a0 = z0[d], a1 = z1[d];
      float b0 = c0[d], b1 = c1[d], b2 = c2[d], b3 = c3[d];
      zc[0][0] = fmaf(a0, b0, zc[0][0]); zc[0][1] = fmaf(a0, b1, zc[0][1]);
      zc[0][2] = fmaf(a0, b2, zc[0][2]); zc[0][3] = fmaf(a0, b3, zc[0][3]);
      zc[1][0] = fmaf(a1, b0, zc[1][0]); zc[1][1] = fmaf(a1, b1, zc[1][1]);
      zc[1][2] = fmaf(a1, b2, zc[1][2]); zc[1][3] = fmaf(a1, b3, zc[1][3]);
    }
#pragma unroll
    for (int nt = 0; nt < 2; ++nt) {
#pragma unroll
      for (int q = 0; q < 4; ++q) {
        const int rh = q >> 1;
        const int row = rh ? row1 : row0;
        const int col = colA + nt * 8 + (q & 1);
        const float gem = acc[mt][nt][q];
        const float zq = zsq[row], cq2 = csqs[col];
        const float zcv = zc[rh][nt * 2 + (q & 1)];
        float dsq = zq + cq2 - 2.f * zcv;
        float denom = (1.f - zq) * (1.f - cq2) + 1e-3f;
        float arg = fmaxf(1.f + 2.f * dsq / denom, 1.001f);
        float dist = logf(arg + sqrtf((arg + 1.f) * (arg - 1.f)));
        float tau = fmaxf(SQRTK * fmaxf(1.f - zq, 1e-3f) * 0.5f, 0.01f);
        float r2 = fminf(zq, 0.999f);
        float invlam = (1.f - r2 + 1e-3f) * 0.5f;
        Sc[row * 65 + col] =
            -dist / tau + (gem + bsm[col]) * invlam * (1.f / SQRTK);
      }
    }
  }
  __syncthreads();

  // ---- softmax + argmax ----
  const bool has_k = (out_size >= BTOT * 64 + BTOT);
  if (tid < 128) {
    float m = -1e30f; int am = 0;
    const float* sr = Sc + tid * 65;
    for (int n = 0; n < 64; ++n) {
      float v = sr[n];
      if (v > m) { m = v; am = n; }
    }
    float s = 0.f;
    for (int n = 0; n < 64; ++n) s += __expf(sr[n] - m);
    rmx[tid] = m;
    riv[tid] = 1.f / s;
    if (has_k) out[BTOT * 64 + r0 + tid] = (float)am;
  }
  __syncthreads();
  for (int i = tid; i < 8192; i += 256) {
    int r = i >> 6, n = i & 63;
    out[(size_t)(r0 + r) * 64 + n] = __expf(Sc[r * 65 + n] - rmx[r]) * riv[r];
  }
}

// ----------------------------------------------------------------------------
extern "C" void kernel_launch(void* const* d_in, const int* in_sizes, int n_in,
                              void* d_out, int out_size) {
  const float* z    = (const float*)d_in[0];
  const float* feat = (const float*)d_in[1];
  const float* qzw  = (const float*)d_in[2];
  const float* qzb  = (const float*)d_in[3];
  const float* qfw  = (const float*)d_in[4];
  const float* qfb  = (const float*)d_in[5];
  const float* qg   = (const float*)d_in[6];
  const float* cq   = (const float*)d_in[7];
  float* out = (float*)d_out;

  prep_fold1<<<PFULL / 32, 256>>>(qzw, qfw, qg, cq);
  prep_fold2<<<NCH, 256>>>();
  prep_small<<<1, 64>>>(cq, qzb, qfb);
  cudaFuncSetAttribute(atlas_main, cudaFuncAttributeMaxDynamicSharedMemorySize,
                       SMEMB);
  atlas_main<<<BTOT / 128, 256, SMEMB>>>(z, feat, cq, out, out_size);
}

// round 7
// speedup vs baseline: 1.4892x; 1.0316x over previous
#include <cuda_runtime.h>
#include <cuda_bf16.h>
#include <cstdint>

#define BTOT 16384
#define PFULL 4416          // 64 z + 256 feat + 4096 zz (full)
#define PW2   2624          // 64 z + 256 feat + 2304 zz (8-aligned tri groups)
#define NGRP  288           // zz groups of 8
#define NCH   41            // PW2 / 64
#define SQRTK 11.313708498984761f

__device__ float g_Wfull[64 * PFULL];
__device__ __align__(16) __nv_bfloat16 g_Wh[64 * PW2];
__device__ __align__(16) __nv_bfloat16 g_Wl[64 * PW2];
__device__ float g_csq[64];
__device__ float g_bsum[64];
__device__ uchar2 g_gij[NGRP];   // per group: (i, j0=8b)

// ---------------- prep stage 1: full fp32 fold over K=128 -------------------
__global__ void prep_fold1(const float* __restrict__ qzw,
                           const float* __restrict__ qfw,
                           const float* __restrict__ qg,
                           const float* __restrict__ cq) {
  __shared__ float cq_s[64 * 128];
  const int tid = threadIdx.x;
  const float4* s4 = (const float4*)cq;
  float4* d4 = (float4*)cq_s;
  for (int i = tid; i < 2048; i += 256) d4[i] = s4[i];
  __syncthreads();

  const int p  = blockIdx.x * 32 + (tid & 7) * 4;   // float4 of p
  const int ng = tid >> 3;                          // 32 groups x 2 charts
  const float* src; int stride, off;
  if (p < 64)       { src = qzw; stride = 64;   off = p; }
  else if (p < 320) { src = qfw; stride = 256;  off = p - 64; }
  else              { src = qg;  stride = 4096; off = p - 320; }

  float acc[2][4] = {};
  for (int k0 = 0; k0 < 128; k0 += 4) {
    float4 wv[4];
#pragma unroll
    for (int kk = 0; kk < 4; ++kk)
      wv[kk] = *(const float4*)(src + (size_t)(k0 + kk) * stride + off);
#pragma unroll
    for (int kk = 0; kk < 4; ++kk) {
#pragma unroll
      for (int j = 0; j < 2; ++j) {
        float cv = cq_s[(ng * 2 + j) * 128 + k0 + kk];
        acc[j][0] = fmaf(cv, wv[kk].x, acc[j][0]);
        acc[j][1] = fmaf(cv, wv[kk].y, acc[j][1]);
        acc[j][2] = fmaf(cv, wv[kk].z, acc[j][2]);
        acc[j][3] = fmaf(cv, wv[kk].w, acc[j][3]);
      }
    }
  }
#pragma unroll
  for (int j = 0; j < 2; ++j)
    *(float4*)(g_Wfull + (size_t)(ng * 2 + j) * PFULL + p) = *(float4*)acc[j];
}

// ------- prep stage 2: symmetric aligned-group fold + hi/lo split -----------
__global__ void prep_fold2() {
  const int tid = threadIdx.x;
  const int pl = blockIdx.x * 64 + (tid & 63);
  const int ng = tid >> 6;                 // 4 groups x 16 charts
  int srcp = -1, srcq = -1;
  if (pl < 320) {
    srcp = pl;
  } else {
    int t = pl - 320;                      // < 2304 always (PW2-320)
    int g = t >> 3, w8 = t & 7;
    int i = 0, cum = 0;
    for (int ii = 0; ii < 64; ++ii) {
      int cnt = 8 - (ii >> 3);
      if (g < cum + cnt) { i = ii; break; }
      cum += cnt;
    }
    int b = (i >> 3) + (g - cum);
    int j = b * 8 + w8;
    if (ng == 0 && w8 == 0)
      g_gij[g] = make_uchar2((unsigned char)i, (unsigned char)(b * 8));
    if (j >= i) {
      srcp = 320 + i * 64 + j;
      srcq = (j > i) ? (320 + j * 64 + i) : -1;
    }
  }
#pragma unroll 4
  for (int jj = 0; jj < 16; ++jj) {
    int n = ng * 16 + jj;
    float v = 0.f;
    if (srcp >= 0) {
      v = g_Wfull[(size_t)n * PFULL + srcp];
      if (srcq >= 0) v += g_Wfull[(size_t)n * PFULL + srcq];
    }
    __nv_bfloat16 h = __float2bfloat16(v);
    g_Wh[(size_t)n * PW2 + pl] = h;
    g_Wl[(size_t)n * PW2 + pl] = __float2bfloat16(v - __bfloat162float(h));
  }
}

__global__ void prep_small(const float* __restrict__ cq,
                           const float* __restrict__ qzb,
                           const float* __restrict__ qfb) {
  int n = threadIdx.x;
  if (n >= 64) return;
  const float* r = cq + n * 128;
  float cs = 0.f, bs = 0.f;
  for (int d = 0; d < 64; ++d) cs = fmaf(r[d], r[d], cs);
  for (int k = 0; k < 128; ++k) bs = fmaf(r[k], qzb[k] + qfb[k], bs);
  g_csq[n] = cs;
  g_bsum[n] = bs;
}

// --------------------------- main kernel ------------------------------------
// 64 rows per CTA, grid 256, 2 CTAs/SM.  smem layout (bytes):
#define O_ZS   0             // float [64][68] = 17408
#define O_CS   17408         // float [64][65] = 16640
#define O_GIJ  34048         // uchar2[288]    = 576
#define O_ZSQ  34624         // float [64]
#define O_CSQ  34880
#define O_BSM  35136
#define O_RMX  35392
#define O_RIV  35648
#define O_XH   35904         // bf16 [2][64][72] = 18432  (Sc overlaps here)
#define O_XL   54336         // bf16 [2][64][72] = 18432
#define O_WH   72768         // bf16 [2][64][72] = 18432
#define O_WL   91200         // bf16 [2][64][72] = 18432
#define SMEMB  109632

__device__ __forceinline__ void mma16816(float* c, const uint32_t* a,
                                         const uint32_t* b) {
  asm volatile(
      "mma.sync.aligned.m16n8k16.row.col.f32.bf16.bf16.f32 "
      "{%0,%1,%2,%3},{%4,%5,%6,%7},{%8,%9},{%0,%1,%2,%3};"
      : "+f"(c[0]), "+f"(c[1]), "+f"(c[2]), "+f"(c[3])
      : "r"(a[0]), "r"(a[1]), "r"(a[2]), "r"(a[3]), "r"(b[0]), "r"(b[1]));
}

__device__ __forceinline__ void ldsm4(uint32_t* r, uint32_t saddr) {
  asm volatile(
      "ldmatrix.sync.aligned.m8n8.x4.shared.b16 {%0,%1,%2,%3},[%4];"
      : "=r"(r[0]), "=r"(r[1]), "=r"(r[2]), "=r"(r[3]) : "r"(saddr));
}

__device__ __forceinline__ void pack_store(__nv_bfloat16* xh, __nv_bfloat16* xl,
                                           const float* v) {
  uint32_t ph[4], plo[4];
#pragma unroll
  for (int j = 0; j < 4; ++j) {
    __nv_bfloat162 h2 = __float22bfloat162_rn(make_float2(v[2 * j], v[2 * j + 1]));
    ph[j] = *(uint32_t*)&h2;
    __nv_bfloat162 l2 = __float22bfloat162_rn(
        make_float2(v[2 * j] - __low2float(h2), v[2 * j + 1] - __high2float(h2)));
    plo[j] = *(uint32_t*)&l2;
  }
  *(uint4*)xh = *(uint4*)ph;
  *(uint4*)xl = *(uint4*)plo;
}

__global__ void __launch_bounds__(256, 2)
atlas_main(const float* __restrict__ z, const float* __restrict__ feat,
           const float* __restrict__ cq, float* __restrict__ out,
           int out_size) {
  extern __shared__ char sm[];
  float* zs = (float*)(sm + O_ZS);                 // stride 68
  float* cs = (float*)(sm + O_CS);                 // stride 65
  uchar2* gij = (uchar2*)(sm + O_GIJ);
  float* zsq  = (float*)(sm + O_ZSQ);
  float* csqs = (float*)(sm + O_CSQ);
  float* bsm  = (float*)(sm + O_BSM);
  float* rmx  = (float*)(sm + O_RMX);
  float* riv  = (float*)(sm + O_RIV);
  float* Sc   = (float*)(sm + O_XH);               // overlap, used post-MMA
  __nv_bfloat16* Xh = (__nv_bfloat16*)(sm + O_XH); // per-buf 4608 elem
  __nv_bfloat16* Xl = (__nv_bfloat16*)(sm + O_XL);
  __nv_bfloat16* Wh = (__nv_bfloat16*)(sm + O_WH); // per-buf 4608 elem
  __nv_bfloat16* Wl = (__nv_bfloat16*)(sm + O_WL);

  const int tid = threadIdx.x, lane = tid & 31, w = tid >> 5;
  const int gid = lane >> 2, tg = lane & 3;
  const int r0 = blockIdx.x * 64;
  const uint32_t smb = (uint32_t)__cvta_generic_to_shared(sm);

  for (int i = tid; i < 1024; i += 256) {          // 64 rows x 16 float4
    int row = i >> 4, q = i & 15;
    *(float4*)(zs + row * 68 + q * 4) =
        ((const float4*)(z + (size_t)(r0 + row) * 64))[q];
  }
  for (int i = tid; i < 4096; i += 256) {
    int n = i >> 6, d = i & 63;
    cs[n * 65 + d] = cq[n * 128 + d];
  }
  for (int i = tid; i < NGRP; i += 256) gij[i] = g_gij[i];
  if (tid < 64) { csqs[tid] = g_csq[tid]; bsm[tid] = g_bsum[tid]; }
  __syncthreads();
  if (tid < 64) {
    float s = 0.f;
    const float* zr = zs + tid * 68;
    for (int d = 0; d < 64; ++d) s = fmaf(zr[d], zr[d], s);
    zsq[tid] = s;
  }

  const int grow = tid >> 2, qtr = tid & 3;        // X-gen role
  const float* zrow = zs + grow * 68;
  const int wrow = tid >> 2, wcol = (tid & 3) * 16; // W-load role

  // prologue: chunk 0 (pure z region) + W0 into buf 0
  {
#pragma unroll
    for (int g = 0; g < 2; ++g) {
      int pb = qtr * 16 + g * 8;
      float v[8];
      float4 u0 = *(const float4*)(zrow + pb);
      float4 u1 = *(const float4*)(zrow + pb + 4);
      v[0] = u0.x; v[1] = u0.y; v[2] = u0.z; v[3] = u0.w;
      v[4] = u1.x; v[5] = u1.y; v[6] = u1.z; v[7] = u1.w;
      pack_store(Xh + grow * 72 + pb, Xl + grow * 72 + pb, v);
    }
    const __nv_bfloat16* gh = g_Wh + (size_t)wrow * PW2 + wcol;
    const __nv_bfloat16* gl = g_Wl + (size_t)wrow * PW2 + wcol;
    *(uint4*)(Wh + wrow * 72 + wcol)     = *(const uint4*)gh;
    *(uint4*)(Wh + wrow * 72 + wcol + 8) = *(const uint4*)(gh + 8);
    *(uint4*)(Wl + wrow * 72 + wcol)     = *(const uint4*)gl;
    *(uint4*)(Wl + wrow * 72 + wcol + 8) = *(const uint4*)(gl + 8);
  }
  __syncthreads();

  const int wm = w >> 2, wn = w & 3;       // 2 x 4 warp grid
  const int m_base = wm * 32, n_base = wn * 16;
  float acc[2][2][4] = {};

  const uint32_t aoff = ((lane & 15) * 72 + (lane >> 4) * 8) * 2;
  const uint32_t boff =
      (((((lane >> 4) << 3)) + (lane & 7)) * 72 + ((lane >> 3) & 1) * 8) * 2;
  const uint32_t XHb = smb + O_XH + m_base * 144 + aoff;
  const uint32_t XLb = smb + O_XL + m_base * 144 + aoff;
  const uint32_t WHb = smb + O_WH + n_base * 144 + boff;
  const uint32_t WLb = smb + O_WL + n_base * 144 + boff;

  for (int c = 0; c < NCH; ++c) {
    const int cb = c & 1, nb = cb ^ 1, cc = c + 1;
    // stage next W chunk (LDG latency hidden under MMAs)
    uint4 whr[2], wlr[2];
    if (cc < NCH) {
      const __nv_bfloat16* gh = g_Wh + (size_t)wrow * PW2 + cc * 64 + wcol;
      const __nv_bfloat16* gl = g_Wl + (size_t)wrow * PW2 + cc * 64 + wcol;
      whr[0] = *(const uint4*)gh; whr[1] = *(const uint4*)(gh + 8);
      wlr[0] = *(const uint4*)gl; wlr[1] = *(const uint4*)(gl + 8);
    }
    // MMA on buf cb (3-pass split, 64-wide K)
    const uint32_t xh0 = XHb + cb * 9216, xl0 = XLb + cb * 9216;
    const uint32_t wh0 = WHb + cb * 9216, wl0 = WLb + cb * 9216;
#pragma unroll
    for (int kh = 0; kh < 4; ++kh) {
      const uint32_t kb = kh * 32;
      uint32_t bh[4], bl[4];
      ldsm4(bh, wh0 + kb);
      ldsm4(bl, wl0 + kb);
#pragma unroll
      for (int mt = 0; mt < 2; ++mt) {
        uint32_t ah[4], al[4];
        ldsm4(ah, xh0 + mt * 2304 + kb);
        ldsm4(al, xl0 + mt * 2304 + kb);
#pragma unroll
        for (int nt = 0; nt < 2; ++nt) {
          mma16816(acc[mt][nt], ah, bh + nt * 2);
          mma16816(acc[mt][nt], ah, bl + nt * 2);
          mma16816(acc[mt][nt], al, bh + nt * 2);
        }
      }
    }
    // produce chunk cc into buf nb
    if (cc < NCH) {
      __nv_bfloat16* xhd = Xh + nb * 4608 + grow * 72 + qtr * 16;
      __nv_bfloat16* xld = Xl + nb * 4608 + grow * 72 + qtr * 16;
      const int pb = cc * 64 + qtr * 16;
#pragma unroll
      for (int g = 0; g < 2; ++g) {
        const int p = pb + g * 8;
        float v[8];
        float4 u0, u1;
        float scale = 1.f;
        if (p < 320) {                     // feat region (chunks 1..4)
          const float* fp = feat + (size_t)(r0 + grow) * 256 + (p - 64);
          u0 = *(const float4*)fp; u1 = *(const float4*)(fp + 4);
        } else {                           // zz aligned-group region
          uchar2 ij = gij[(p - 320) >> 3];
          scale = zrow[ij.x];
          u0 = *(const float4*)(zrow + ij.y);
          u1 = *(const float4*)(zrow + ij.y + 4);
        }
        v[0] = scale * u0.x; v[1] = scale * u0.y;
        v[2] = scale * u0.z; v[3] = scale * u0.w;
        v[4] = scale * u1.x; v[5] = scale * u1.y;
        v[6] = scale * u1.z; v[7] = scale * u1.w;
        pack_store(xhd + g * 8, xld + g * 8, v);
      }
      *(uint4*)(Wh + nb * 4608 + wrow * 72 + wcol)     = whr[0];
      *(uint4*)(Wh + nb * 4608 + wrow * 72 + wcol + 8) = whr[1];
      *(uint4*)(Wl + nb * 4608 + wrow * 72 + wcol)     = wlr[0];
      *(uint4*)(Wl + nb * 4608 + wrow * 72 + wcol + 8) = wlr[1];
    }
    __syncthreads();
  }

  // ---- epilogue: fp32 z.c, hyperbolic score (Sc overlaps dead X buffer) ----
  const int colA = n_base + tg * 2;
#pragma unroll
  for (int mt = 0; mt < 2; ++mt) {
    const int row0 = m_base + mt * 16 + gid, row1 = row0 + 8;
    float zc[2][4] = {{0, 0, 0, 0}, {0, 0, 0, 0}};
    const float* z0 = zs + row0 * 68;
    const float* z1 = zs + row1 * 68;
    const float* c0 = cs + (colA)     * 65;
    const float* c1 = cs + (colA + 1) * 65;
    const float* c2 = cs + (colA + 8) * 65;
    const float* c3 = cs + (colA + 9) * 65;
    for (int d = 0; d < 64; ++d) {
      float a0 = z0[d], a1 = z1[d];
      float b0 = c0[d], b1 = c1[d], b2 = c2[d], b3 = c3[d];
      zc[0][0] = fmaf(a0, b0, zc[0][0]); zc[0][1] = fmaf(a0, b1, zc[0][1]);
      zc[0][2] = fmaf(a0, b2, zc[0][2]); zc[0][3] = fmaf(a0, b3, zc[0][3]);
      zc[1][0] = fmaf(a1, b0, zc[1][0]); zc[1][1] = fmaf(a1, b1, zc[1][1]);
      zc[1][2] = fmaf(a1, b2, zc[1][2]); zc[1][3] = fmaf(a1, b3, zc[1][3]);
    }
#pragma unroll
    for (int nt = 0; nt < 2; ++nt) {
#pragma unroll
      for (int q = 0; q < 4; ++q) {
        const int rh = q >> 1;
        const int row = rh ? row1 : row0;
        const int col = colA + nt * 8 + (q & 1);
        const float gem = acc[mt][nt][q];
        const float zq = zsq[row], cq2 = csqs[col];
        const float zcv = zc[rh][nt * 2 + (q & 1)];
        float dsq = zq + cq2 - 2.f * zcv;
        float denom = (1.f - zq) * (1.f - cq2) + 1e-3f;
        float arg = fmaxf(1.f + 2.f * dsq / denom, 1.001f);
        float dist = logf(arg + sqrtf((arg + 1.f) * (arg - 1.f)));
        float tau = fmaxf(SQRTK * fmaxf(1.f - zq, 1e-3f) * 0.5f, 0.01f);
        float r2 = fminf(zq, 0.999f);
        float invlam = (1.f - r2 + 1e-3f) * 0.5f;
        Sc[row * 65 + col] =
            -dist / tau + (gem + bsm[col]) * invlam * (1.f / SQRTK);
      }
    }
  }
  __syncthreads();

  // ---- softmax + argmax ----
  const bool has_k = (out_size >= BTOT * 64 + BTOT);
  if (tid < 64) {
    float m = -1e30f; int am = 0;
    const float* sr = Sc + tid * 65;
    for (int n = 0; n < 64; ++n) {
      float v = sr[n];
      if (v > m) { m = v; am = n; }
    }
    float s = 0.f;
    for (int n = 0; n < 64; ++n) s += __expf(sr[n] - m);
    rmx[tid] = m;
    riv[tid] = 1.f / s;
    if (has_k) out[BTOT * 64 + r0 + tid] = (float)am;
  }
  __syncthreads();
  for (int i = tid; i < 4096; i += 256) {
    int r = i >> 6, n = i & 63;
    out[(size_t)(r0 + r) * 64 + n] = __expf(Sc[r * 65 + n] - rmx[r]) * riv[r];
  }
}

// ----------------------------------------------------------------------------
extern "C" void kernel_launch(void* const* d_in, const int* in_sizes, int n_in,
                              void* d_out, int out_size) {
  const float* z    = (const float*)d_in[0];
  const float* feat = (const float*)d_in[1];
  const float* qzw  = (const float*)d_in[2];
  const float* qzb  = (const float*)d_in[3];
  const float* qfw  = (const float*)d_in[4];
  const float* qfb  = (const float*)d_in[5];
  const float* qg   = (const float*)d_in[6];
  const float* cq   = (const float*)d_in[7];
  float* out = (float*)d_out;

  prep_fold1<<<PFULL / 32, 256>>>(qzw, qfw, qg, cq);
  prep_fold2<<<NCH, 256>>>();
  prep_small<<<1, 64>>>(cq, qzb, qfb);
  cudaFuncSetAttribute(atlas_main, cudaFuncAttributeMaxDynamicSharedMemorySize,
                       SMEMB);
  atlas_main<<<BTOT / 64, 256, SMEMB>>>(z, feat, cq, out, out_size);
}